// round 11
// baseline (speedup 1.0000x reference)
#include <cuda_runtime.h>

#define IMG_H 512
#define IMG_W 512
#define OUT_H 502
#define OUT_W 502
#define N_IMG 48
#define N_PIX (N_IMG * IMG_H * IMG_W)
#define N_OUT_D 12096192.0
#define TX 32
#define TY 54
#define H_REAL 64           // TY + 10 rows of horizontal results
#define H_ROWS 66           // + 2 zero pad rows for the tail warp group
#define HP_W 68             // 32 col-pairs (64 floats) + 4 pad
#define H4_W 36
#define GRID_X 16
#define GRID_Y 10           // ceil(502/54)
#define TOTAL_BLOCKS (GRID_X * GRID_Y * N_IMG)   // 7680
#define MM_GRID 592         // ~4 blocks/SM: places as wave 1, k_ssim fills around it

__device__ double gSum = 0.0;
__device__ unsigned int gCount = 0u;
__device__ unsigned int gMaxKey = 0u;
__device__ unsigned int gMinKey = 0xFFFFFFFFu;
__device__ unsigned int gMMdone = 0u;

__device__ __forceinline__ unsigned int fkey(float f) {
    unsigned int u = __float_as_uint(f);
    return (u & 0x80000000u) ? ~u : (u | 0x80000000u);
}
__device__ __forceinline__ float funkey(unsigned int u) {
    return __uint_as_float((u & 0x80000000u) ? (u ^ 0x80000000u) : ~u);
}

__global__ __launch_bounds__(256) void k_minmax(const float* __restrict__ x, int n4) {
    cudaTriggerProgrammaticLaunchCompletion();

    float vmin = 3.4e38f, vmax = -3.4e38f;
    int idx = blockIdx.x * blockDim.x + threadIdx.x;
    int stride = gridDim.x * blockDim.x;
    const float4* x4 = (const float4*)x;
    #pragma unroll 8
    for (int i = idx; i < n4; i += stride) {
        float4 v = x4[i];
        vmin = fminf(vmin, fminf(fminf(v.x, v.y), fminf(v.z, v.w)));
        vmax = fmaxf(vmax, fmaxf(fmaxf(v.x, v.y), fmaxf(v.z, v.w)));
    }
    #pragma unroll
    for (int o = 16; o; o >>= 1) {
        vmin = fminf(vmin, __shfl_xor_sync(0xffffffffu, vmin, o));
        vmax = fmaxf(vmax, __shfl_xor_sync(0xffffffffu, vmax, o));
    }
    __shared__ float smin[8], smax[8];
    int lane = threadIdx.x & 31, wid = threadIdx.x >> 5;
    if (lane == 0) { smin[wid] = vmin; smax[wid] = vmax; }
    __syncthreads();
    if (threadIdx.x == 0) {
        float bmin = smin[0], bmax = smax[0];
        #pragma unroll
        for (int i = 1; i < 8; i++) {
            bmin = fminf(bmin, smin[i]);
            bmax = fmaxf(bmax, smax[i]);
        }
        atomicMax(&gMaxKey, fkey(bmax));
        atomicMin(&gMinKey, fkey(bmin));
        __threadfence();
        atomicAdd(&gMMdone, 1u);   // publish block completion
    }
}

__global__ __launch_bounds__(256, 4) void k_ssim(const float* __restrict__ P,
                                                 const float* __restrict__ T,
                                                 float* __restrict__ out) {
    constexpr float W[11] = {
        0.00102837f, 0.00759869f, 0.03600077f, 0.10936070f, 0.21300560f,
        0.26601173f,
        0.21300560f, 0.10936070f, 0.03600077f, 0.00759869f, 0.00102837f
    };

    __shared__ float h01[H_ROWS][HP_W];   // interleaved (mu1, mu2) per column
    __shared__ float h23[H_ROWS][HP_W];   // interleaved (e11, e22) per column
    __shared__ float h4[H_ROWS][H4_W];    // e12 scalar
    __shared__ float wsum[8];

    const int img = blockIdx.z;
    const int ox0 = blockIdx.x * TX;
    const int oy0 = blockIdx.y * TY;
    const float* __restrict__ p = P + img * (IMG_H * IMG_W);
    const float* __restrict__ t = T + img * (IMG_H * IMG_W);
    const int tid = threadIdx.x;
    const int tx = tid & 31, ty8 = tid >> 5;

    // zero the two pad rows (64, 65) of each h array
    if (tid < 2 * HP_W) {
        (&h01[H_REAL][0])[tid] = 0.f;
        (&h23[H_REAL][0])[tid] = 0.f;
    }
    if (tid < 2 * H4_W) (&h4[H_REAL][0])[tid] = 0.f;

    // ---- horizontal 11-tap pass: 64 rows x 8 col-groups = 512 items = 2 sweeps ----
    #pragma unroll
    for (int it = 0; it < 2; it++) {
        const int item = tid + (it << 8);
        const int r = item >> 3;             // 0..63
        const int c0 = (item & 7) << 2;      // 0,4,...,28
        const int gr = min(oy0 + r, IMG_H - 1);
        const float* prow = p + gr * IMG_W;
        const float* trow = t + gr * IMG_W;

        float4 qp[4], qt[4];
        #pragma unroll
        for (int ch = 0; ch < 4; ch++) {
            int gc = min(ox0 + c0 + (ch << 2), IMG_W - 4);  // clamped: garbage only feeds masked outputs
            qp[ch] = *reinterpret_cast<const float4*>(prow + gc);
            qt[ch] = *reinterpret_cast<const float4*>(trow + gc);
        }

        float a0[4] = {0.f, 0.f, 0.f, 0.f};
        float a1[4] = {0.f, 0.f, 0.f, 0.f};
        float a2[4] = {0.f, 0.f, 0.f, 0.f};
        float a3[4] = {0.f, 0.f, 0.f, 0.f};
        float a4[4] = {0.f, 0.f, 0.f, 0.f};
        #pragma unroll
        for (int ch = 0; ch < 4; ch++) {
            float vpc[4] = {qp[ch].x, qp[ch].y, qp[ch].z, qp[ch].w};
            float vtc[4] = {qt[ch].x, qt[ch].y, qt[ch].z, qt[ch].w};
            #pragma unroll
            for (int jv = 0; jv < 4; jv++) {
                const int j = (ch << 2) + jv;
                if (j < 14) {
                    float vp = vpc[jv], vt = vtc[jv];
                    float pp = vp * vp;
                    float tt = vt * vt;
                    float pt = vp * vt;
                    #pragma unroll
                    for (int u = 0; u < 4; u++) {
                        const int k = j - u;
                        if (k >= 0 && k < 11) {
                            a0[u] = fmaf(vp, W[k], a0[u]);
                            a1[u] = fmaf(vt, W[k], a1[u]);
                            a2[u] = fmaf(pp, W[k], a2[u]);
                            a3[u] = fmaf(tt, W[k], a3[u]);
                            a4[u] = fmaf(pt, W[k], a4[u]);
                        }
                    }
                }
            }
        }
        *reinterpret_cast<float4*>(&h01[r][2 * c0])     = make_float4(a0[0], a1[0], a0[1], a1[1]);
        *reinterpret_cast<float4*>(&h01[r][2 * c0 + 4]) = make_float4(a0[2], a1[2], a0[3], a1[3]);
        *reinterpret_cast<float4*>(&h23[r][2 * c0])     = make_float4(a2[0], a3[0], a2[1], a3[1]);
        *reinterpret_cast<float4*>(&h23[r][2 * c0 + 4]) = make_float4(a2[2], a3[2], a2[3], a3[3]);
        *reinterpret_cast<float4*>(&h4[r][c0]) = make_float4(a4[0], a4[1], a4[2], a4[3]);
    }
    __syncthreads();

    // ---- vertical 11-tap pass: 7 consecutive rows per thread ----
    const int r0 = ty8 * 7;   // 0,7,...,49 (rows 54,55 of group 7 masked)
    float m1[7]  = {0.f, 0.f, 0.f, 0.f, 0.f, 0.f, 0.f};
    float m2[7]  = {0.f, 0.f, 0.f, 0.f, 0.f, 0.f, 0.f};
    float e11[7] = {0.f, 0.f, 0.f, 0.f, 0.f, 0.f, 0.f};
    float e22[7] = {0.f, 0.f, 0.f, 0.f, 0.f, 0.f, 0.f};
    float e12[7] = {0.f, 0.f, 0.f, 0.f, 0.f, 0.f, 0.f};
    const float2* c01 = reinterpret_cast<const float2*>(&h01[r0][2 * tx]);
    const float2* c23 = reinterpret_cast<const float2*>(&h23[r0][2 * tx]);
    const float* c4 = &h4[r0][tx];
    #pragma unroll
    for (int i = 0; i < 17; i++) {
        float2 q01 = c01[i * (HP_W / 2)];
        float2 q23 = c23[i * (HP_W / 2)];
        float q4 = c4[i * H4_W];
        #pragma unroll
        for (int u = 0; u < 7; u++) {
            const int k = i - u;
            if (k >= 0 && k < 11) {
                m1[u]  = fmaf(q01.x, W[k], m1[u]);
                m2[u]  = fmaf(q01.y, W[k], m2[u]);
                e11[u] = fmaf(q23.x, W[k], e11[u]);
                e22[u] = fmaf(q23.y, W[k], e22[u]);
                e12[u] = fmaf(q4,    W[k], e12[u]);
            }
        }
    }

    // ---- wait for min/max publication (spin: data-dependent, cannot be hoisted) ----
    if (tid == 0) {
        while (*reinterpret_cast<volatile unsigned int*>(&gMMdone) < MM_GRID)
            __nanosleep(64);
    }
    __syncthreads();
    __threadfence();
    const float L = funkey(*reinterpret_cast<volatile unsigned int*>(&gMaxKey)) -
                    funkey(*reinterpret_cast<volatile unsigned int*>(&gMinKey));
    const float C1 = (0.01f * L) * (0.01f * L);
    const float C2 = (0.03f * L) * (0.03f * L);

    float localsum = 0.f;
    const int ox = ox0 + tx;
    #pragma unroll
    for (int u = 0; u < 7; u++) {
        int lr = r0 + u;
        int oy = oy0 + lr;
        if (lr < TY && oy < OUT_H && ox < OUT_W) {
            float mu1s = m1[u] * m1[u];
            float mu2s = m2[u] * m2[u];
            float mu12 = m1[u] * m2[u];
            float s1 = e11[u] - mu1s;
            float s2 = e22[u] - mu2s;
            float s12 = e12[u] - mu12;
            float v1 = 2.f * s12 + C2;
            float v2 = s1 + s2 + C2;
            float num = (2.f * mu12 + C1) * v1;
            float den = (mu1s + mu2s + C1) * v2;
            localsum += __fdividef(num, den);
        }
    }

    // ---- block reduce, double atomic accumulate, last block finalizes ----
    #pragma unroll
    for (int o = 16; o; o >>= 1)
        localsum += __shfl_xor_sync(0xffffffffu, localsum, o);
    if ((tid & 31) == 0) wsum[tid >> 5] = localsum;
    __syncthreads();
    if (tid == 0) {
        float s = 0.f;
        #pragma unroll
        for (int i = 0; i < 8; i++) s += wsum[i];
        atomicAdd(&gSum, (double)s);
        __threadfence();
        unsigned int old = atomicAdd(&gCount, 1u);
        if (old == TOTAL_BLOCKS - 1) {
            double v = atomicAdd(&gSum, 0.0);
            out[0] = (float)(-v / N_OUT_D);
            gSum = 0.0;
            gCount = 0u;
            gMaxKey = 0u;
            gMinKey = 0xFFFFFFFFu;
            gMMdone = 0u;
        }
    }
}

extern "C" void kernel_launch(void* const* d_in, const int* in_sizes, int n_in,
                              void* d_out, int out_size) {
    const float* y_pred = (const float*)d_in[0];
    const float* y_true = (const float*)d_in[1];
    float* out = (float*)d_out;

    k_minmax<<<MM_GRID, 256>>>(y_pred, N_PIX / 4);

    // PDL: allow k_ssim's grid to launch while the scan runs; ordering is
    // enforced by the gMMdone spin in the epilogue (not griddepcontrol.wait,
    // which ptxas may hoist to kernel entry).
    cudaLaunchConfig_t cfg = {};
    cfg.gridDim = dim3(GRID_X, GRID_Y, N_IMG);
    cfg.blockDim = dim3(256, 1, 1);
    cfg.dynamicSmemBytes = 0;
    cudaLaunchAttribute attr[1];
    attr[0].id = cudaLaunchAttributeProgrammaticStreamSerialization;
    attr[0].val.programmaticStreamSerializationAllowed = 1;
    cfg.attrs = attr;
    cfg.numAttrs = 1;
    cudaLaunchKernelEx(&cfg, k_ssim, y_pred, y_true, out);
}

// round 12
// speedup vs baseline: 1.1245x; 1.1245x over previous
#include <cuda_runtime.h>

#define IMG_H 512
#define IMG_W 512
#define OUT_H 502
#define OUT_W 502
#define N_IMG 48
#define N_PIX (N_IMG * IMG_H * IMG_W)
#define N_OUT_D 12096192.0
#define TX 32
#define TY 56
#define H_REAL 66           // TY + 10 rows of horizontal results (no padding needed)
#define HP_W 68             // 32 col-pairs (64 floats) + 4 pad
#define H4_W 36
#define GRID_X 16
#define GRID_Y 9            // 9 * 56 = 504 >= 502
#define TOTAL_BLOCKS (GRID_X * GRID_Y * N_IMG)   // 6912
#define H_ITEMS (H_REAL * 8)                     // 528 horizontal work items

__device__ double gSum = 0.0;
__device__ unsigned int gCount = 0u;
__device__ unsigned int gMaxKey = 0u;
__device__ unsigned int gMinKey = 0xFFFFFFFFu;

__device__ __forceinline__ unsigned int fkey(float f) {
    unsigned int u = __float_as_uint(f);
    return (u & 0x80000000u) ? ~u : (u | 0x80000000u);
}
__device__ __forceinline__ float funkey(unsigned int u) {
    return __uint_as_float((u & 0x80000000u) ? (u ^ 0x80000000u) : ~u);
}

__global__ __launch_bounds__(256) void k_minmax(const float* __restrict__ x, int n4) {
    cudaTriggerProgrammaticLaunchCompletion();

    float vmin = 3.4e38f, vmax = -3.4e38f;
    int idx = blockIdx.x * blockDim.x + threadIdx.x;
    int stride = gridDim.x * blockDim.x;
    const float4* x4 = (const float4*)x;
    for (int i = idx; i < n4; i += stride) {
        float4 v = x4[i];
        vmin = fminf(vmin, fminf(fminf(v.x, v.y), fminf(v.z, v.w)));
        vmax = fmaxf(vmax, fmaxf(fmaxf(v.x, v.y), fmaxf(v.z, v.w)));
    }
    #pragma unroll
    for (int o = 16; o; o >>= 1) {
        vmin = fminf(vmin, __shfl_xor_sync(0xffffffffu, vmin, o));
        vmax = fmaxf(vmax, __shfl_xor_sync(0xffffffffu, vmax, o));
    }
    __shared__ float smin[8], smax[8];
    int lane = threadIdx.x & 31, wid = threadIdx.x >> 5;
    if (lane == 0) { smin[wid] = vmin; smax[wid] = vmax; }
    __syncthreads();
    if (threadIdx.x == 0) {
        float bmin = smin[0], bmax = smax[0];
        #pragma unroll
        for (int i = 1; i < 8; i++) {
            bmin = fminf(bmin, smin[i]);
            bmax = fmaxf(bmax, smax[i]);
        }
        atomicMax(&gMaxKey, fkey(bmax));
        atomicMin(&gMinKey, fkey(bmin));
    }
}

__global__ __launch_bounds__(256, 4) void k_ssim(const float* __restrict__ P,
                                                 const float* __restrict__ T,
                                                 float* __restrict__ out) {
    constexpr float W[11] = {
        0.00102837f, 0.00759869f, 0.03600077f, 0.10936070f, 0.21300560f,
        0.26601173f,
        0.21300560f, 0.10936070f, 0.03600077f, 0.00759869f, 0.00102837f
    };

    __shared__ float h01[H_REAL][HP_W];   // interleaved (mu1, mu2) per column
    __shared__ float h23[H_REAL][HP_W];   // interleaved (e11, e22) per column
    __shared__ float h4[H_REAL][H4_W];    // e12 scalar
    __shared__ float wsum[8];

    const int img = blockIdx.z;
    const int ox0 = blockIdx.x * TX;
    const int oy0 = blockIdx.y * TY;
    const float* __restrict__ p = P + img * (IMG_H * IMG_W);
    const float* __restrict__ t = T + img * (IMG_H * IMG_W);
    const int tid = threadIdx.x;
    const int tx = tid & 31, ty8 = tid >> 5;

    // ---- horizontal 11-tap pass: 66 rows x 8 col-groups = 528 items ----
    #pragma unroll
    for (int it = 0; it < 3; it++) {
        const int item = tid + (it << 8);
        if (item < H_ITEMS) {
            const int r = item >> 3;             // 0..65
            const int c0 = (item & 7) << 2;      // 0,4,...,28
            const int gr = min(oy0 + r, IMG_H - 1);   // clamped rows feed only masked outputs
            const float* prow = p + gr * IMG_W;
            const float* trow = t + gr * IMG_W;

            float4 qp[4], qt[4];
            #pragma unroll
            for (int ch = 0; ch < 4; ch++) {
                int gc = min(ox0 + c0 + (ch << 2), IMG_W - 4);  // clamped: feeds only masked outputs
                qp[ch] = *reinterpret_cast<const float4*>(prow + gc);
                qt[ch] = *reinterpret_cast<const float4*>(trow + gc);
            }

            float a0[4] = {0.f, 0.f, 0.f, 0.f};
            float a1[4] = {0.f, 0.f, 0.f, 0.f};
            float a2[4] = {0.f, 0.f, 0.f, 0.f};
            float a3[4] = {0.f, 0.f, 0.f, 0.f};
            float a4[4] = {0.f, 0.f, 0.f, 0.f};
            #pragma unroll
            for (int ch = 0; ch < 4; ch++) {
                float vpc[4] = {qp[ch].x, qp[ch].y, qp[ch].z, qp[ch].w};
                float vtc[4] = {qt[ch].x, qt[ch].y, qt[ch].z, qt[ch].w};
                #pragma unroll
                for (int jv = 0; jv < 4; jv++) {
                    const int j = (ch << 2) + jv;
                    if (j < 14) {
                        float vp = vpc[jv], vt = vtc[jv];
                        float pp = vp * vp;
                        float tt = vt * vt;
                        float pt = vp * vt;
                        #pragma unroll
                        for (int u = 0; u < 4; u++) {
                            const int k = j - u;
                            if (k >= 0 && k < 11) {
                                a0[u] = fmaf(vp, W[k], a0[u]);
                                a1[u] = fmaf(vt, W[k], a1[u]);
                                a2[u] = fmaf(pp, W[k], a2[u]);
                                a3[u] = fmaf(tt, W[k], a3[u]);
                                a4[u] = fmaf(pt, W[k], a4[u]);
                            }
                        }
                    }
                }
            }
            *reinterpret_cast<float4*>(&h01[r][2 * c0])     = make_float4(a0[0], a1[0], a0[1], a1[1]);
            *reinterpret_cast<float4*>(&h01[r][2 * c0 + 4]) = make_float4(a0[2], a1[2], a0[3], a1[3]);
            *reinterpret_cast<float4*>(&h23[r][2 * c0])     = make_float4(a2[0], a3[0], a2[1], a3[1]);
            *reinterpret_cast<float4*>(&h23[r][2 * c0 + 4]) = make_float4(a2[2], a3[2], a2[3], a3[3]);
            *reinterpret_cast<float4*>(&h4[r][c0]) = make_float4(a4[0], a4[1], a4[2], a4[3]);
        }
    }
    __syncthreads();

    // ---- vertical 11-tap pass: 7 consecutive rows per thread, 8x7 = 56 = TY exact ----
    const int r0 = ty8 * 7;   // 0,7,...,49
    float m1[7]  = {0.f, 0.f, 0.f, 0.f, 0.f, 0.f, 0.f};
    float m2[7]  = {0.f, 0.f, 0.f, 0.f, 0.f, 0.f, 0.f};
    float e11[7] = {0.f, 0.f, 0.f, 0.f, 0.f, 0.f, 0.f};
    float e22[7] = {0.f, 0.f, 0.f, 0.f, 0.f, 0.f, 0.f};
    float e12[7] = {0.f, 0.f, 0.f, 0.f, 0.f, 0.f, 0.f};
    const float2* c01 = reinterpret_cast<const float2*>(&h01[r0][2 * tx]);
    const float2* c23 = reinterpret_cast<const float2*>(&h23[r0][2 * tx]);
    const float* c4 = &h4[r0][tx];
    #pragma unroll
    for (int i = 0; i < 17; i++) {
        float2 q01 = c01[i * (HP_W / 2)];
        float2 q23 = c23[i * (HP_W / 2)];
        float q4 = c4[i * H4_W];
        #pragma unroll
        for (int u = 0; u < 7; u++) {
            const int k = i - u;
            if (k >= 0 && k < 11) {
                m1[u]  = fmaf(q01.x, W[k], m1[u]);
                m2[u]  = fmaf(q01.y, W[k], m2[u]);
                e11[u] = fmaf(q23.x, W[k], e11[u]);
                e22[u] = fmaf(q23.y, W[k], e22[u]);
                e12[u] = fmaf(q4,    W[k], e12[u]);
            }
        }
    }

    // ---- wait for k_minmax completion ----
    cudaGridDependencySynchronize();
    const float L = funkey(*reinterpret_cast<volatile unsigned int*>(&gMaxKey)) -
                    funkey(*reinterpret_cast<volatile unsigned int*>(&gMinKey));
    const float C1 = (0.01f * L) * (0.01f * L);
    const float C2 = (0.03f * L) * (0.03f * L);

    float localsum = 0.f;
    const int ox = ox0 + tx;
    #pragma unroll
    for (int u = 0; u < 7; u++) {
        int oy = oy0 + r0 + u;
        if (oy < OUT_H && ox < OUT_W) {
            float mu1s = m1[u] * m1[u];
            float mu2s = m2[u] * m2[u];
            float mu12 = m1[u] * m2[u];
            float s1 = e11[u] - mu1s;
            float s2 = e22[u] - mu2s;
            float s12 = e12[u] - mu12;
            float v1 = 2.f * s12 + C2;
            float v2 = s1 + s2 + C2;
            float num = (2.f * mu12 + C1) * v1;
            float den = (mu1s + mu2s + C1) * v2;
            localsum += __fdividef(num, den);
        }
    }

    // ---- block reduce, double atomic accumulate, last block finalizes ----
    #pragma unroll
    for (int o = 16; o; o >>= 1)
        localsum += __shfl_xor_sync(0xffffffffu, localsum, o);
    if ((tid & 31) == 0) wsum[tid >> 5] = localsum;
    __syncthreads();
    if (tid == 0) {
        float s = 0.f;
        #pragma unroll
        for (int i = 0; i < 8; i++) s += wsum[i];
        atomicAdd(&gSum, (double)s);
        __threadfence();
        unsigned int old = atomicAdd(&gCount, 1u);
        if (old == TOTAL_BLOCKS - 1) {
            double v = atomicAdd(&gSum, 0.0);
            out[0] = (float)(-v / N_OUT_D);
            gSum = 0.0;
            gCount = 0u;
            gMaxKey = 0u;
            gMinKey = 0xFFFFFFFFu;
        }
    }
}

extern "C" void kernel_launch(void* const* d_in, const int* in_sizes, int n_in,
                              void* d_out, int out_size) {
    const float* y_pred = (const float*)d_in[0];
    const float* y_true = (const float*)d_in[1];
    float* out = (float*)d_out;

    k_minmax<<<1024, 256>>>(y_pred, N_PIX / 4);

    cudaLaunchConfig_t cfg = {};
    cfg.gridDim = dim3(GRID_X, GRID_Y, N_IMG);
    cfg.blockDim = dim3(256, 1, 1);
    cfg.dynamicSmemBytes = 0;
    cudaLaunchAttribute attr[1];
    attr[0].id = cudaLaunchAttributeProgrammaticStreamSerialization;
    attr[0].val.programmaticStreamSerializationAllowed = 1;
    cfg.attrs = attr;
    cfg.numAttrs = 1;
    cudaLaunchKernelEx(&cfg, k_ssim, y_pred, y_true, out);
}